// round 3
// baseline (speedup 1.0000x reference)
#include <cuda_runtime.h>

// ---------------------------------------------------------------------------
// CrossAttention: out = softmax((Q @ (K Wk + bk)^T)/sqrt(Dq)) @ (V Wv + bv) @ Wo + bo
// B=8, Lq=Lkv=2048, Dq=512, Dc=768. All fp32.
// ---------------------------------------------------------------------------

#define BATCH 8
#define L_Q   2048
#define L_KV  2048
#define D_Q   512
#define D_C   768

// Scratch (device globals; no allocation in kernel_launch).
__device__ float g_kproj[BATCH * L_KV * D_Q];                 //  33.5 MB
__device__ float g_vproj[BATCH * L_KV * D_Q];                 //  33.5 MB
__device__ float g_scores[(size_t)BATCH * L_Q * L_KV];        // 134.2 MB
__device__ float g_ctx[BATCH * L_Q * D_Q];                    //  33.5 MB

// ---------------------------------------------------------------------------
// 128x128x8 SIMT fp32 GEMM. 256 threads, each computes an 8x8 micro-tile
// split as 2x2 groups of 4x4 (rows ty*4 / 64+ty*4, cols tx*4 / 64+tx*4).
// A: row-major [M,K].
// B: TRANS_B=false -> row-major [K,N];  TRANS_B=true -> row-major [N,K] (C=A@B^T).
// C: row-major [M,N].  C = alpha*(A@B(^T)) + bias[n]  (bias may be null).
// Requires M%128==0, N%128==0, K%8==0 (all shapes here satisfy this).
// blockIdx.z = batch, with element strides strideA/B/C.
// ---------------------------------------------------------------------------
template <bool TRANS_B>
__global__ void __launch_bounds__(256)
sgemm128(const float* __restrict__ A, const float* __restrict__ B,
         float* __restrict__ C, const float* __restrict__ bias,
         int M, int N, int K, float alpha,
         long strideA, long strideB, long strideC)
{
    __shared__ float As[8][128];
    __shared__ float Bs[8][128];

    const int tid = threadIdx.x;
    const int bm = blockIdx.y * 128;
    const int bn = blockIdx.x * 128;

    A += (long)blockIdx.z * strideA;
    B += (long)blockIdx.z * strideB;
    C += (long)blockIdx.z * strideC;

    const int ty = tid >> 4;        // 0..15
    const int tx = tid & 15;        // 0..15

    // A-tile loader: 128 rows x 8 cols, one float4 per thread.
    const int arow = tid >> 1;            // 0..127
    const int acol = (tid & 1) * 4;       // 0 or 4
    // B-tile loader (NN): 8 rows x 128 cols, one float4 per thread.
    const int brow = tid >> 5;            // 0..7
    const int bcol = (tid & 31) * 4;      // 0..124

    const float* Aptr = A + (long)(bm + arow) * K + acol;
    const float* BptrT = TRANS_B ? (B + (long)(bn + arow) * K + acol) : nullptr;
    const float* BptrN = TRANS_B ? nullptr : (B + (long)brow * N + bn + bcol);

    float acc[8][8];
    #pragma unroll
    for (int i = 0; i < 8; i++)
        #pragma unroll
        for (int j = 0; j < 8; j++) acc[i][j] = 0.0f;

    float ar[8], br[8];

    for (int k0 = 0; k0 < K; k0 += 8) {
        // Load A tile transposed into As[k][m].
        float4 av = *(const float4*)(Aptr + k0);
        As[acol + 0][arow] = av.x;
        As[acol + 1][arow] = av.y;
        As[acol + 2][arow] = av.z;
        As[acol + 3][arow] = av.w;
        if (TRANS_B) {
            float4 bv = *(const float4*)(BptrT + k0);
            Bs[acol + 0][arow] = bv.x;
            Bs[acol + 1][arow] = bv.y;
            Bs[acol + 2][arow] = bv.z;
            Bs[acol + 3][arow] = bv.w;
        } else {
            float4 bv = *(const float4*)(BptrN + (long)k0 * N);
            *(float4*)&Bs[brow][bcol] = bv;
        }
        __syncthreads();

        #pragma unroll
        for (int kk = 0; kk < 8; kk++) {
            *(float4*)&ar[0] = *(const float4*)&As[kk][ty * 4];
            *(float4*)&ar[4] = *(const float4*)&As[kk][64 + ty * 4];
            *(float4*)&br[0] = *(const float4*)&Bs[kk][tx * 4];
            *(float4*)&br[4] = *(const float4*)&Bs[kk][64 + tx * 4];
            #pragma unroll
            for (int i = 0; i < 8; i++)
                #pragma unroll
                for (int j = 0; j < 8; j++)
                    acc[i][j] = fmaf(ar[i], br[j], acc[i][j]);
        }
        __syncthreads();
    }

    // Epilogue: alpha scale + optional bias.
    #pragma unroll
    for (int i = 0; i < 8; i++) {
        const int m = bm + ((i < 4) ? (ty * 4 + i) : (64 + ty * 4 + (i - 4)));
        #pragma unroll
        for (int jg = 0; jg < 2; jg++) {
            const int n = bn + jg * 64 + tx * 4;
            float4 v;
            v.x = acc[i][jg * 4 + 0] * alpha;
            v.y = acc[i][jg * 4 + 1] * alpha;
            v.z = acc[i][jg * 4 + 2] * alpha;
            v.w = acc[i][jg * 4 + 3] * alpha;
            if (bias) {
                v.x += bias[n + 0];
                v.y += bias[n + 1];
                v.z += bias[n + 2];
                v.w += bias[n + 3];
            }
            *(float4*)(C + (long)m * N + n) = v;
        }
    }
}

// ---------------------------------------------------------------------------
// Row softmax over rows of length 2048. One block (256 threads) per row.
// ---------------------------------------------------------------------------
__global__ void __launch_bounds__(256)
softmax_rows2048(float* __restrict__ S)
{
    float* p = S + (size_t)blockIdx.x * 2048;
    const int t = threadIdx.x;

    float v[8];
    float mx = -1e30f;
    #pragma unroll
    for (int i = 0; i < 8; i++) {
        v[i] = p[t + i * 256];
        mx = fmaxf(mx, v[i]);
    }

    __shared__ float red[8];
    #pragma unroll
    for (int o = 16; o > 0; o >>= 1)
        mx = fmaxf(mx, __shfl_xor_sync(0xFFFFFFFFu, mx, o));
    if ((t & 31) == 0) red[t >> 5] = mx;
    __syncthreads();
    float rowmax = red[0];
    #pragma unroll
    for (int w = 1; w < 8; w++) rowmax = fmaxf(rowmax, red[w]);
    __syncthreads();

    float sum = 0.0f;
    #pragma unroll
    for (int i = 0; i < 8; i++) {
        v[i] = __expf(v[i] - rowmax);
        sum += v[i];
    }
    #pragma unroll
    for (int o = 16; o > 0; o >>= 1)
        sum += __shfl_xor_sync(0xFFFFFFFFu, sum, o);
    if ((t & 31) == 0) red[t >> 5] = sum;
    __syncthreads();
    float rowsum = 0.0f;
    #pragma unroll
    for (int w = 0; w < 8; w++) rowsum += red[w];

    const float inv = 1.0f / rowsum;
    #pragma unroll
    for (int i = 0; i < 8; i++)
        p[t + i * 256] = v[i] * inv;
}

// ---------------------------------------------------------------------------
// Launcher
// ---------------------------------------------------------------------------
extern "C" void kernel_launch(void* const* d_in, const int* in_sizes, int n_in,
                              void* d_out, int out_size)
{
    const float* query = (const float*)d_in[0];  // [8,2048,512]
    const float* key   = (const float*)d_in[1];  // [8,2048,768]
    const float* value = (const float*)d_in[2];  // [8,2048,768]
    const float* Wk    = (const float*)d_in[3];  // [768,512]
    const float* bk    = (const float*)d_in[4];  // [512]
    const float* Wv    = (const float*)d_in[5];  // [768,512]
    const float* bv    = (const float*)d_in[6];  // [512]
    const float* Wo    = (const float*)d_in[7];  // [512,512]
    const float* bo    = (const float*)d_in[8];  // [512]
    float* out = (float*)d_out;                  // [8,2048,512]

    float *kproj, *vproj, *scores, *ctx;
    cudaGetSymbolAddress((void**)&kproj,  g_kproj);
    cudaGetSymbolAddress((void**)&vproj,  g_vproj);
    cudaGetSymbolAddress((void**)&scores, g_scores);
    cudaGetSymbolAddress((void**)&ctx,    g_ctx);

    const float scale = 1.0f / sqrtf((float)D_Q);

    // 1) K projection: [B*Lkv, Dc] @ [Dc, Dq] + bk  -> kproj
    {
        dim3 grid(D_Q / 128, (BATCH * L_KV) / 128, 1);
        sgemm128<false><<<grid, 256>>>(key, Wk, kproj, bk,
                                       BATCH * L_KV, D_Q, D_C, 1.0f, 0, 0, 0);
    }
    // 2) V projection -> vproj
    {
        dim3 grid(D_Q / 128, (BATCH * L_KV) / 128, 1);
        sgemm128<false><<<grid, 256>>>(value, Wv, vproj, bv,
                                       BATCH * L_KV, D_Q, D_C, 1.0f, 0, 0, 0);
    }
    // 3) Scores: per-batch Q[2048,512] @ kproj[2048,512]^T * scale -> scores
    {
        dim3 grid(L_KV / 128, L_Q / 128, BATCH);
        sgemm128<true><<<grid, 256>>>(query, kproj, scores, nullptr,
                                      L_Q, L_KV, D_Q, scale,
                                      (long)L_Q * D_Q, (long)L_KV * D_Q,
                                      (long)L_Q * L_KV);
    }
    // 4) Softmax over last dim (rows of 2048)
    {
        softmax_rows2048<<<BATCH * L_Q, 256>>>(scores);
    }
    // 5) Context: per-batch weights[2048,2048] @ vproj[2048,512] -> ctx
    {
        dim3 grid(D_Q / 128, L_Q / 128, BATCH);
        sgemm128<false><<<grid, 256>>>(scores, vproj, ctx, nullptr,
                                       L_Q, D_Q, L_KV, 1.0f,
                                       (long)L_Q * L_KV, (long)L_KV * D_Q,
                                       (long)L_Q * D_Q);
    }
    // 6) Output projection: [B*Lq, Dq] @ Wo + bo -> out
    {
        dim3 grid(D_Q / 128, (BATCH * L_Q) / 128, 1);
        sgemm128<false><<<grid, 256>>>(ctx, Wo, out, bo,
                                       BATCH * L_Q, D_Q, D_Q, 1.0f, 0, 0, 0);
    }
}

// round 5
// speedup vs baseline: 3.0755x; 3.0755x over previous
#include <cuda_runtime.h>

// ---------------------------------------------------------------------------
// CrossAttention: out = softmax((Q @ (K Wk + bk)^T)/sqrt(Dq)) @ (V Wv + bv) @ Wo + bo
// B=8, Lq=Lkv=2048, Dq=512, Dc=768. fp32 in/out, TF32 tensor-core GEMMs.
// ---------------------------------------------------------------------------

#define BATCH 8
#define L_Q   2048
#define L_KV  2048
#define D_Q   512
#define D_C   768

// Scratch (device globals; no allocation in kernel_launch).
__device__ float g_kproj[BATCH * L_KV * D_Q];
__device__ float g_vproj[BATCH * L_KV * D_Q];
__device__ float g_scores[(size_t)BATCH * L_Q * L_KV];
__device__ float g_ctx[BATCH * L_Q * D_Q];

// ---------------------------------------------------------------------------
// PTX helpers
// ---------------------------------------------------------------------------
__device__ __forceinline__ unsigned f2tf32(float x) {
    unsigned u;
    asm("cvt.rna.tf32.f32 %0, %1;" : "=r"(u) : "f"(x));
    return u;
}

__device__ __forceinline__ void mma_tf32(float c[4], const unsigned a[4], const unsigned b[2]) {
    asm volatile(
        "mma.sync.aligned.m16n8k8.row.col.f32.tf32.tf32.f32 "
        "{%0,%1,%2,%3}, {%4,%5,%6,%7}, {%8,%9}, {%0,%1,%2,%3};"
        : "+f"(c[0]), "+f"(c[1]), "+f"(c[2]), "+f"(c[3])
        : "r"(a[0]), "r"(a[1]), "r"(a[2]), "r"(a[3]), "r"(b[0]), "r"(b[1]));
}

__device__ __forceinline__ void cp_async16(void* smem_dst, const void* gmem_src) {
    unsigned s = (unsigned)__cvta_generic_to_shared(smem_dst);
    asm volatile("cp.async.cg.shared.global [%0], [%1], 16;" :: "r"(s), "l"(gmem_src));
}
#define CP_COMMIT() asm volatile("cp.async.commit_group;")
#define CP_WAIT1()  asm volatile("cp.async.wait_group 1;")
#define CP_WAIT0()  asm volatile("cp.async.wait_group 0;")

// ---------------------------------------------------------------------------
// TF32 tensor-core GEMM. Block tile 128x128xBK32, 256 threads (8 warps 2x4),
// warp tile 64x32 (4x4 m16n8k8 MMAs per k=8 step). 2-stage cp.async pipeline.
// A: row-major [M,K].
// TRANS_B=false: B row-major [K,N] (C = A@B). TRANS_B=true: B row-major [N,K]
// (C = A@B^T). C row-major [M,N]. C = alpha*prod + bias[n] (bias optional).
// Requires M%128==0, N%128==0, K%32==0 (all shapes here qualify).
// blockIdx.z batches via element strides sA/sB/sC.
//
// Smem layouts (floats):
//   As  [2][128][36]   (pad 4: frag banks = 4g+t, conflict-free)
//   Bs  TRANS_B: [2][128][36]  (n-major rows, same layout/loader as A)
//       else:    [2][32][136]  (pad 8: frag banks = 8t+g, conflict-free)
// ---------------------------------------------------------------------------
#define ASTR 36
#define BSTR_NN 136

template <bool TRANS_B>
__global__ void __launch_bounds__(256, 2)
tgemm128(const float* __restrict__ A, const float* __restrict__ B,
         float* __restrict__ C, const float* __restrict__ bias,
         int M, int N, int K, float alpha,
         long sA, long sB, long sC)
{
    extern __shared__ float sm[];
    float* As = sm;                           // 2*128*36
    float* Bs = sm + 2 * 128 * ASTR;          // 2*128*36 or 2*32*136

    const int tid  = threadIdx.x;
    const int lane = tid & 31;
    const int warp = tid >> 5;
    const int g = lane >> 2;      // 0..7
    const int t = lane & 3;       // 0..3
    const int mw = (warp >> 2) * 64;   // warp M offset (0,64)
    const int nw = (warp & 3) * 32;    // warp N offset (0..96)

    const int bm = blockIdx.y * 128;
    const int bn = blockIdx.x * 128;

    A += (long)blockIdx.z * sA;
    B += (long)blockIdx.z * sB;
    C += (long)blockIdx.z * sC;

    // --- global->smem loaders (one 128x32 tile each, 4 float4 per thread) ---
    // A-style tile (also used for TRANS_B B): 128 rows x 32 floats.
    const int ar  = tid >> 3;           // 0..31 (then +32,+64,+96)
    const int ac4 = (tid & 7) * 4;      // float col 0..28
    // NN B tile: 32 rows x 128 floats.
    const int br  = tid >> 5;           // 0..7 (then +8,+16,+24)
    const int bc4 = (tid & 31) * 4;     // float col 0..124

    const float* Ag = A + (long)(bm + ar) * K + ac4;
    const float* Bg = TRANS_B ? (B + (long)(bn + ar) * K + ac4)
                              : (B + (long)br * N + bn + bc4);

    float acc[4][4][4];
    #pragma unroll
    for (int i = 0; i < 4; i++)
        #pragma unroll
        for (int j = 0; j < 4; j++)
            #pragma unroll
            for (int r = 0; r < 4; r++) acc[i][j][r] = 0.0f;

    auto load_stage = [&](int s, int k0) {
        float* ad = As + s * 128 * ASTR + ar * ASTR + ac4;
        #pragma unroll
        for (int it = 0; it < 4; it++)
            cp_async16(ad + it * 32 * ASTR, Ag + k0 + (long)it * 32 * K);
        if (TRANS_B) {
            float* bd = Bs + s * 128 * ASTR + ar * ASTR + ac4;
            #pragma unroll
            for (int it = 0; it < 4; it++)
                cp_async16(bd + it * 32 * ASTR, Bg + k0 + (long)it * 32 * K);
        } else {
            float* bd = Bs + s * 32 * BSTR_NN + br * BSTR_NN + bc4;
            #pragma unroll
            for (int it = 0; it < 4; it++)
                cp_async16(bd + it * 8 * BSTR_NN, Bg + (long)(k0 + it * 8) * N);
        }
    };

    load_stage(0, 0);
    CP_COMMIT();

    const int nk = K / 32;
    for (int kt = 0; kt < nk; kt++) {
        const int s = kt & 1;
        if (kt + 1 < nk) {
            load_stage(s ^ 1, (kt + 1) * 32);
            CP_COMMIT();
            CP_WAIT1();
        } else {
            CP_WAIT0();
        }
        __syncthreads();

        const float* a = As + s * 128 * ASTR;
        const float* b = TRANS_B ? (Bs + s * 128 * ASTR) : (Bs + s * 32 * BSTR_NN);

        #pragma unroll
        for (int kk = 0; kk < 32; kk += 8) {
            unsigned af[4][4];
            #pragma unroll
            for (int i = 0; i < 4; i++) {
                const float* row0 = a + (mw + 16 * i + g) * ASTR + kk + t;
                const float* row1 = row0 + 8 * ASTR;
                af[i][0] = f2tf32(row0[0]);
                af[i][1] = f2tf32(row1[0]);
                af[i][2] = f2tf32(row0[4]);
                af[i][3] = f2tf32(row1[4]);
            }
            unsigned bf[4][2];
            #pragma unroll
            for (int j = 0; j < 4; j++) {
                if (TRANS_B) {
                    const float* rb = b + (nw + 8 * j + g) * ASTR + kk + t;
                    bf[j][0] = f2tf32(rb[0]);
                    bf[j][1] = f2tf32(rb[4]);
                } else {
                    const float* cb = b + (kk + t) * BSTR_NN + nw + 8 * j + g;
                    bf[j][0] = f2tf32(cb[0]);
                    bf[j][1] = f2tf32(cb[4 * BSTR_NN]);
                }
            }
            #pragma unroll
            for (int i = 0; i < 4; i++)
                #pragma unroll
                for (int j = 0; j < 4; j++)
                    mma_tf32(acc[i][j], af[i], bf[j]);
        }
        __syncthreads();
    }

    // --- epilogue: alpha + bias, float2 stores (full 32B sectors) ---
    #pragma unroll
    for (int i = 0; i < 4; i++) {
        const int r0 = bm + mw + 16 * i + g;
        #pragma unroll
        for (int j = 0; j < 4; j++) {
            const int c0 = bn + nw + 8 * j + 2 * t;
            float bx = 0.0f, by = 0.0f;
            if (bias) { bx = bias[c0]; by = bias[c0 + 1]; }
            float2 v0, v1;
            v0.x = acc[i][j][0] * alpha + bx;
            v0.y = acc[i][j][1] * alpha + by;
            v1.x = acc[i][j][2] * alpha + bx;
            v1.y = acc[i][j][3] * alpha + by;
            *(float2*)(C + (long)r0 * N + c0)       = v0;
            *(float2*)(C + (long)(r0 + 8) * N + c0) = v1;
        }
    }
}

// ---------------------------------------------------------------------------
// Row softmax over rows of length 2048. One block (256 threads) per row.
// ---------------------------------------------------------------------------
__global__ void __launch_bounds__(256)
softmax_rows2048(float* __restrict__ S)
{
    float* p = S + (size_t)blockIdx.x * 2048;
    const int t = threadIdx.x;

    float v[8];
    float mx = -1e30f;
    #pragma unroll
    for (int i = 0; i < 8; i++) {
        v[i] = p[t + i * 256];
        mx = fmaxf(mx, v[i]);
    }

    __shared__ float red[8];
    #pragma unroll
    for (int o = 16; o > 0; o >>= 1)
        mx = fmaxf(mx, __shfl_xor_sync(0xFFFFFFFFu, mx, o));
    if ((t & 31) == 0) red[t >> 5] = mx;
    __syncthreads();
    float rowmax = red[0];
    #pragma unroll
    for (int w = 1; w < 8; w++) rowmax = fmaxf(rowmax, red[w]);
    __syncthreads();

    float sum = 0.0f;
    #pragma unroll
    for (int i = 0; i < 8; i++) {
        v[i] = __expf(v[i] - rowmax);
        sum += v[i];
    }
    #pragma unroll
    for (int o = 16; o > 0; o >>= 1)
        sum += __shfl_xor_sync(0xFFFFFFFFu, sum, o);
    if ((t & 31) == 0) red[t >> 5] = sum;
    __syncthreads();
    float rowsum = 0.0f;
    #pragma unroll
    for (int w = 0; w < 8; w++) rowsum += red[w];

    const float inv = 1.0f / rowsum;
    #pragma unroll
    for (int i = 0; i < 8; i++)
        p[t + i * 256] = v[i] * inv;
}

// ---------------------------------------------------------------------------
// Launcher
// ---------------------------------------------------------------------------
extern "C" void kernel_launch(void* const* d_in, const int* in_sizes, int n_in,
                              void* d_out, int out_size)
{
    const float* query = (const float*)d_in[0];  // [8,2048,512]
    const float* key   = (const float*)d_in[1];  // [8,2048,768]
    const float* value = (const float*)d_in[2];  // [8,2048,768]
    const float* Wk    = (const float*)d_in[3];  // [768,512]
    const float* bk    = (const float*)d_in[4];  // [512]
    const float* Wv    = (const float*)d_in[5];  // [768,512]
    const float* bv    = (const float*)d_in[6];  // [512]
    const float* Wo    = (const float*)d_in[7];  // [512,512]
    const float* bo    = (const float*)d_in[8];  // [512]
    float* out = (float*)d_out;                  // [8,2048,512]

    float *kproj, *vproj, *scores, *ctx;
    cudaGetSymbolAddress((void**)&kproj,  g_kproj);
    cudaGetSymbolAddress((void**)&vproj,  g_vproj);
    cudaGetSymbolAddress((void**)&scores, g_scores);
    cudaGetSymbolAddress((void**)&ctx,    g_ctx);

    const float scale = 1.0f / sqrtf((float)D_Q);

    // Dynamic smem sizes (floats -> bytes)
    const int smem_nn = (2 * 128 * ASTR + 2 * 32 * BSTR_NN) * 4;   // ~70.5 KB
    const int smem_tr = (2 * 128 * ASTR + 2 * 128 * ASTR) * 4;     // 72 KB
    static bool attr_done = false;
    if (!attr_done) {
        cudaFuncSetAttribute(tgemm128<false>,
                             cudaFuncAttributeMaxDynamicSharedMemorySize, smem_nn);
        cudaFuncSetAttribute(tgemm128<true>,
                             cudaFuncAttributeMaxDynamicSharedMemorySize, smem_tr);
        attr_done = true;
    }

    // 1) K projection: [B*Lkv, Dc] @ [Dc, Dq] + bk -> kproj
    {
        dim3 grid(D_Q / 128, (BATCH * L_KV) / 128, 1);
        tgemm128<false><<<grid, 256, smem_nn>>>(key, Wk, kproj, bk,
                                                BATCH * L_KV, D_Q, D_C, 1.0f, 0, 0, 0);
    }
    // 2) V projection -> vproj
    {
        dim3 grid(D_Q / 128, (BATCH * L_KV) / 128, 1);
        tgemm128<false><<<grid, 256, smem_nn>>>(value, Wv, vproj, bv,
                                                BATCH * L_KV, D_Q, D_C, 1.0f, 0, 0, 0);
    }
    // 3) Scores: per-batch Q[2048,512] @ kproj[2048,512]^T * scale -> scores
    {
        dim3 grid(L_KV / 128, L_Q / 128, BATCH);
        tgemm128<true><<<grid, 256, smem_tr>>>(query, kproj, scores, nullptr,
                                               L_Q, L_KV, D_Q, scale,
                                               (long)L_Q * D_Q, (long)L_KV * D_Q,
                                               (long)L_Q * L_KV);
    }
    // 4) Softmax over last dim (rows of 2048)
    {
        softmax_rows2048<<<BATCH * L_Q, 256>>>(scores);
    }
    // 5) Context: per-batch weights[2048,2048] @ vproj[2048,512] -> ctx
    {
        dim3 grid(D_Q / 128, L_Q / 128, BATCH);
        tgemm128<false><<<grid, 256, smem_nn>>>(scores, vproj, ctx, nullptr,
                                                L_Q, D_Q, L_KV, 1.0f,
                                                (long)L_Q * L_KV, (long)L_KV * D_Q,
                                                (long)L_Q * D_Q);
    }
    // 6) Output projection: [B*Lq, Dq] @ Wo + bo -> out
    {
        dim3 grid(D_Q / 128, (BATCH * L_Q) / 128, 1);
        tgemm128<false><<<grid, 256, smem_nn>>>(ctx, Wo, out, bo,
                                                BATCH * L_Q, D_Q, D_Q, 1.0f, 0, 0, 0);
    }
}

// round 7
// speedup vs baseline: 4.3617x; 1.4182x over previous
#include <cuda_runtime.h>
#include <cuda_fp16.h>
#include <cstdint>

// ---------------------------------------------------------------------------
// CrossAttention via fp16 mma.sync.m16n8k16 (fp32 accumulate) NT GEMMs.
// out = softmax((Q @ (K Wk + bk)^T)/sqrt(Dq)) @ (V Wv + bv) @ Wo + bo
// B=8, Lq=Lkv=2048, Dq=512, Dc=768. fp32 I/O; operands rounded to fp16
// (11-bit mantissa == tf32) which round-5 showed gives rel_err ~5.6e-4.
// ---------------------------------------------------------------------------

#define BATCH 8
#define L_Q   2048
#define L_KV  2048
#define D_Q   512
#define D_C   768
#define MKV   (BATCH * L_KV)   // 16384

// Scratch (device globals).
__device__ __align__(128) __half g_keyh [MKV * D_C];
__device__ __align__(128) __half g_valh [MKV * D_C];
__device__ __align__(128) __half g_qh   [BATCH * L_Q * D_Q];
__device__ __align__(128) __half g_wkT  [D_Q * D_C];
__device__ __align__(128) __half g_wvT  [D_Q * D_C];
__device__ __align__(128) __half g_woT  [D_Q * D_Q];
__device__ __align__(128) __half g_kproj[MKV * D_Q];
__device__ __align__(128) __half g_vprT [D_Q * MKV];              // [Dq][B*Lkv]
__device__ __align__(128) float  g_scores[(size_t)BATCH * L_Q * L_KV];
__device__ __align__(128) __half g_probs[(size_t)BATCH * L_Q * L_KV];
__device__ __align__(128) __half g_ctxh [BATCH * L_Q * D_Q];

// ---------------------------------------------------------------------------
// PTX helpers
// ---------------------------------------------------------------------------
__device__ __forceinline__ uint32_t smem_u32(const void* p) {
    uint32_t a;
    asm("{ .reg .u64 t; cvta.to.shared.u64 t, %1; cvt.u32.u64 %0, t; }"
        : "=r"(a) : "l"(p));
    return a;
}
__device__ __forceinline__ void cp16(uint32_t s, const void* g) {
    asm volatile("cp.async.cg.shared.global [%0], [%1], 16;" :: "r"(s), "l"(g));
}
#define CP_COMMIT()  asm volatile("cp.async.commit_group;")
#define CP_WAIT(n)   asm volatile("cp.async.wait_group %0;" :: "n"(n))

__device__ __forceinline__ void ldsm_x4(uint32_t r[4], uint32_t addr) {
    asm volatile("ldmatrix.sync.aligned.m8n8.x4.shared.b16 {%0,%1,%2,%3}, [%4];"
                 : "=r"(r[0]), "=r"(r[1]), "=r"(r[2]), "=r"(r[3]) : "r"(addr));
}
__device__ __forceinline__ void mma_f16(float c[4], const uint32_t a[4],
                                        uint32_t b0, uint32_t b1) {
    asm volatile(
        "mma.sync.aligned.m16n8k16.row.col.f32.f16.f16.f32 "
        "{%0,%1,%2,%3}, {%4,%5,%6,%7}, {%8,%9}, {%0,%1,%2,%3};"
        : "+f"(c[0]), "+f"(c[1]), "+f"(c[2]), "+f"(c[3])
        : "r"(a[0]), "r"(a[1]), "r"(a[2]), "r"(a[3]), "r"(b0), "r"(b1));
}

// ---------------------------------------------------------------------------
// fp16 NT GEMM: C[M,N] = A[M,K] @ B[N,K]^T (+ bias).
// BM=128, BN=128, BK=64. 256 threads (8 warps 2x4), warp tile 64x32.
// Smem rows: 64 halves + 8 pad = 72 halves = 144B (16B-mult, ldmatrix
// conflict-free: 8 consecutive rows hit banks 4i..4i+3). 4-stage cp.async.
// OUT_HALF: write __half2; else fp32 float2.
// ROWBIAS: bias indexed by m-row (for transposed-output GEMMs); else by n.
// Requires M%128==0, N%128==0, K%64==0, K/64 >= 3.
// ---------------------------------------------------------------------------
#define HBM 128
#define HBK 64
#define ROWB 144                      // bytes per smem row (72 halves)
#define STG_A (128 * ROWB)            // 18432
#define STG   (2 * STG_A)             // 36864 (A + B)
#define NSTAGE 4
#define SMEM_BYTES (NSTAGE * STG)     // 147456

template <bool OUT_HALF, bool ROWBIAS>
__global__ void __launch_bounds__(256, 1)
gemm_h(const __half* __restrict__ A, const __half* __restrict__ B,
       void* __restrict__ Cv, const float* __restrict__ bias,
       int M, int N, int K, int ldA, int ldB, int ldC,
       long sA, long sB, long sC)
{
    extern __shared__ char smem[];
    const uint32_t sbase = smem_u32(smem);

    const int tid  = threadIdx.x;
    const int lane = tid & 31;
    const int warp = tid >> 5;
    const int g = lane >> 2;            // 0..7
    const int t = lane & 3;             // 0..3
    const int mw = (warp >> 2) * 64;    // warp M offset (0,64)
    const int nw = (warp & 3) * 32;     // warp N offset (0..96)

    const int bm = blockIdx.y * HBM;
    const int bn = blockIdx.x * HBM;
    A += (long)blockIdx.z * sA;
    B += (long)blockIdx.z * sB;

    // Loader: 128 rows x 8 x 16B chunks per tile; 4 chunks/thread/tile.
    const int cu = tid & 7;             // 16B chunk in row
    const int r0 = tid >> 3;            // 0..31

    const int nk = K / HBK;

    auto load_tile = [&](int kt) {
        const int s = kt & (NSTAGE - 1);
        const uint32_t as = sbase + s * STG;
        const uint32_t bs = as + STG_A;
        const long kof = (long)kt * HBK + cu * 8;
        #pragma unroll
        for (int i = 0; i < 4; i++) {
            const int r = r0 + 32 * i;
            cp16(as + r * ROWB + cu * 16, A + (long)(bm + r) * ldA + kof);
            cp16(bs + r * ROWB + cu * 16, B + (long)(bn + r) * ldB + kof);
        }
        CP_COMMIT();
    };

    float acc[4][4][4];
    #pragma unroll
    for (int i = 0; i < 4; i++)
        #pragma unroll
        for (int j = 0; j < 4; j++)
            #pragma unroll
            for (int r = 0; r < 4; r++) acc[i][j][r] = 0.0f;

    load_tile(0); load_tile(1); load_tile(2);

    // ldmatrix per-lane offsets.
    const int lrow = lane & 15;
    const int lkb  = (lane >> 4) * 16;        // byte offset for k-half select
    uint32_t aoff[4], boff[2];
    #pragma unroll
    for (int i = 0; i < 4; i++) aoff[i] = (mw + 16 * i + lrow) * ROWB + lkb;
    #pragma unroll
    for (int jj = 0; jj < 2; jj++) boff[jj] = (nw + 16 * jj + lrow) * ROWB + lkb;

    for (int kt = 0; kt < nk; kt++) {
        CP_WAIT(2);
        __syncthreads();
        if (kt + 3 < nk) load_tile(kt + 3);

        const int s = kt & (NSTAGE - 1);
        const uint32_t as = sbase + s * STG;
        const uint32_t bs = as + STG_A;

        #pragma unroll
        for (int kh = 0; kh < 4; kh++) {          // 4 x k16
            uint32_t a[4][4], b[2][4];
            #pragma unroll
            for (int i = 0; i < 4; i++) ldsm_x4(a[i], as + aoff[i] + kh * 32);
            #pragma unroll
            for (int jj = 0; jj < 2; jj++) ldsm_x4(b[jj], bs + boff[jj] + kh * 32);
            #pragma unroll
            for (int i = 0; i < 4; i++) {
                mma_f16(acc[i][0], a[i], b[0][0], b[0][2]);
                mma_f16(acc[i][1], a[i], b[0][1], b[0][3]);
                mma_f16(acc[i][2], a[i], b[1][0], b[1][2]);
                mma_f16(acc[i][3], a[i], b[1][1], b[1][3]);
            }
        }
        __syncthreads();
    }

    // ----- epilogue -----
    #pragma unroll
    for (int i = 0; i < 4; i++) {
        const int r = bm + mw + 16 * i + g;
        float brow0 = 0.0f, brow1 = 0.0f;
        if (ROWBIAS && bias) { brow0 = bias[r]; brow1 = bias[r + 8]; }
        #pragma unroll
        for (int j = 0; j < 4; j++) {
            const int c = bn + nw + 8 * j + 2 * t;
            float bc0 = 0.0f, bc1 = 0.0f;
            if (!ROWBIAS && bias) { bc0 = bias[c]; bc1 = bias[c + 1]; }
            const float v00 = acc[i][j][0] + (ROWBIAS ? brow0 : bc0);
            const float v01 = acc[i][j][1] + (ROWBIAS ? brow0 : bc1);
            const float v10 = acc[i][j][2] + (ROWBIAS ? brow1 : bc0);
            const float v11 = acc[i][j][3] + (ROWBIAS ? brow1 : bc1);
            if (OUT_HALF) {
                __half* C = (__half*)Cv + (long)blockIdx.z * sC;
                *(__half2*)(C + (long)r * ldC + c)       = __floats2half2_rn(v00, v01);
                *(__half2*)(C + (long)(r + 8) * ldC + c) = __floats2half2_rn(v10, v11);
            } else {
                float* C = (float*)Cv + (long)blockIdx.z * sC;
                *(float2*)(C + (long)r * ldC + c)       = make_float2(v00, v01);
                *(float2*)(C + (long)(r + 8) * ldC + c) = make_float2(v10, v11);
            }
        }
    }
}

// ---------------------------------------------------------------------------
// fp32 -> fp16 convert (optionally scaled). n % 8 == 0.
// ---------------------------------------------------------------------------
__global__ void __launch_bounds__(256)
f32_to_f16(__half* __restrict__ dst, const float* __restrict__ src,
           int n8, float scale)
{
    for (int i = blockIdx.x * blockDim.x + threadIdx.x; i < n8;
         i += gridDim.x * blockDim.x) {
        float4 v0 = ((const float4*)src)[2 * i];
        float4 v1 = ((const float4*)src)[2 * i + 1];
        __half2 h[4];
        h[0] = __floats2half2_rn(v0.x * scale, v0.y * scale);
        h[1] = __floats2half2_rn(v0.z * scale, v0.w * scale);
        h[2] = __floats2half2_rn(v1.x * scale, v1.y * scale);
        h[3] = __floats2half2_rn(v1.z * scale, v1.w * scale);
        ((uint4*)dst)[i] = *(uint4*)h;
    }
}

// ---------------------------------------------------------------------------
// Weight transpose + convert: dst_h[N,K] = (half)src[K,N].  K,N % 32 == 0.
// ---------------------------------------------------------------------------
__global__ void __launch_bounds__(256)
transpose_h(__half* __restrict__ dst, const float* __restrict__ src, int K, int N)
{
    __shared__ float tile[32][33];
    const int n0 = blockIdx.x * 32;
    const int k0 = blockIdx.y * 32;
    const int tx = threadIdx.x & 31;
    const int ty = threadIdx.x >> 5;
    #pragma unroll
    for (int i = 0; i < 32; i += 8)
        tile[ty + i][tx] = src[(long)(k0 + ty + i) * N + n0 + tx];
    __syncthreads();
    #pragma unroll
    for (int i = 0; i < 32; i += 8)
        dst[(long)(n0 + ty + i) * K + k0 + tx] = __float2half(tile[tx][ty + i]);
}

// ---------------------------------------------------------------------------
// Row softmax over 2048-length rows, fp32 in, fp16 out.
// ---------------------------------------------------------------------------
__global__ void __launch_bounds__(256)
softmax_rows2048(const float* __restrict__ S, __half* __restrict__ P)
{
    const float* p = S + (size_t)blockIdx.x * 2048;
    __half* q = P + (size_t)blockIdx.x * 2048;
    const int t = threadIdx.x;

    float v[8];
    float mx = -1e30f;
    #pragma unroll
    for (int i = 0; i < 8; i++) {
        v[i] = p[t + i * 256];
        mx = fmaxf(mx, v[i]);
    }
    __shared__ float red[8];
    #pragma unroll
    for (int o = 16; o > 0; o >>= 1)
        mx = fmaxf(mx, __shfl_xor_sync(0xFFFFFFFFu, mx, o));
    if ((t & 31) == 0) red[t >> 5] = mx;
    __syncthreads();
    float rowmax = red[0];
    #pragma unroll
    for (int w = 1; w < 8; w++) rowmax = fmaxf(rowmax, red[w]);
    __syncthreads();

    float sum = 0.0f;
    #pragma unroll
    for (int i = 0; i < 8; i++) {
        v[i] = __expf(v[i] - rowmax);
        sum += v[i];
    }
    #pragma unroll
    for (int o = 16; o > 0; o >>= 1)
        sum += __shfl_xor_sync(0xFFFFFFFFu, sum, o);
    if ((t & 31) == 0) red[t >> 5] = sum;
    __syncthreads();
    float rowsum = 0.0f;
    #pragma unroll
    for (int w = 0; w < 8; w++) rowsum += red[w];

    const float inv = 1.0f / rowsum;
    #pragma unroll
    for (int i = 0; i < 8; i++)
        q[t + i * 256] = __float2half(v[i] * inv);
}

// ---------------------------------------------------------------------------
// Launcher
// ---------------------------------------------------------------------------
extern "C" void kernel_launch(void* const* d_in, const int* in_sizes, int n_in,
                              void* d_out, int out_size)
{
    const float* query = (const float*)d_in[0];
    const float* key   = (const float*)d_in[1];
    const float* value = (const float*)d_in[2];
    const float* Wk    = (const float*)d_in[3];
    const float* bk    = (const float*)d_in[4];
    const float* Wv    = (const float*)d_in[5];
    const float* bv    = (const float*)d_in[6];
    const float* Wo    = (const float*)d_in[7];
    const float* bo    = (const float*)d_in[8];
    float* out = (float*)d_out;

    __half *keyh, *valh, *qh, *wkT, *wvT, *woT, *kproj, *vprT, *probs, *ctxh;
    float *scores;
    cudaGetSymbolAddress((void**)&keyh,  g_keyh);
    cudaGetSymbolAddress((void**)&valh,  g_valh);
    cudaGetSymbolAddress((void**)&qh,    g_qh);
    cudaGetSymbolAddress((void**)&wkT,   g_wkT);
    cudaGetSymbolAddress((void**)&wvT,   g_wvT);
    cudaGetSymbolAddress((void**)&woT,   g_woT);
    cudaGetSymbolAddress((void**)&kproj, g_kproj);
    cudaGetSymbolAddress((void**)&vprT,  g_vprT);
    cudaGetSymbolAddress((void**)&scores, g_scores);
    cudaGetSymbolAddress((void**)&probs, g_probs);
    cudaGetSymbolAddress((void**)&ctxh,  g_ctxh);

    static bool attr_done = false;
    if (!attr_done) {
        cudaFuncSetAttribute(gemm_h<true, false>,
                             cudaFuncAttributeMaxDynamicSharedMemorySize, SMEM_BYTES);
        cudaFuncSetAttribute(gemm_h<true, true>,
                             cudaFuncAttributeMaxDynamicSharedMemorySize, SMEM_BYTES);
        cudaFuncSetAttribute(gemm_h<false, false>,
                             cudaFuncAttributeMaxDynamicSharedMemorySize, SMEM_BYTES);
        attr_done = true;
    }

    const float scale = 1.0f / sqrtf((float)D_Q);

    // 0) fp16 conversions (scale folded into Q).
    f32_to_f16<<<512, 256>>>(keyh, key,   MKV * D_C / 8, 1.0f);
    f32_to_f16<<<512, 256>>>(valh, value, MKV * D_C / 8, 1.0f);
    f32_to_f16<<<512, 256>>>(qh,   query, BATCH * L_Q * D_Q / 8, scale);
    transpose_h<<<dim3(D_Q / 32, D_C / 32), 256>>>(wkT, Wk, D_C, D_Q);
    transpose_h<<<dim3(D_Q / 32, D_C / 32), 256>>>(wvT, Wv, D_C, D_Q);
    transpose_h<<<dim3(D_Q / 32, D_Q / 32), 256>>>(woT, Wo, D_Q, D_Q);

    // 1) K projection: kproj[16384,512] = keyh @ wkT^T + bk (col bias), half out.
    gemm_h<true, false><<<dim3(D_Q / HBM, MKV / HBM, 1), 256, SMEM_BYTES>>>(
        keyh, wkT, kproj, bk, MKV, D_Q, D_C, D_C, D_C, D_Q, 0, 0, 0);

    // 2) V projection TRANSPOSED: vprT[512,16384] = wvT @ valh^T + bv (ROW bias).
    gemm_h<true, true><<<dim3(MKV / HBM, D_Q / HBM, 1), 256, SMEM_BYTES>>>(
        wvT, valh, vprT, bv, D_Q, MKV, D_C, D_C, D_C, MKV, 0, 0, 0);

    // 3) Scores per batch: qh_b[2048,512] @ kproj_b^T -> fp32 (scale pre-folded).
    gemm_h<false, false><<<dim3(L_KV / HBM, L_Q / HBM, BATCH), 256, SMEM_BYTES>>>(
        qh, kproj, scores, nullptr, L_Q, L_KV, D_Q, D_Q, D_Q, L_KV,
        (long)L_Q * D_Q, (long)L_KV * D_Q, (long)L_Q * L_KV);

    // 4) Softmax -> fp16 probs.
    softmax_rows2048<<<BATCH * L_Q, 256>>>(scores, probs);

    // 5) Context per batch: probs_b[2048,2048] @ (vprT[:, b])^T -> ctxh, half out.
    gemm_h<true, false><<<dim3(D_Q / HBM, L_Q / HBM, BATCH), 256, SMEM_BYTES>>>(
        probs, vprT, ctxh, nullptr, L_Q, D_Q, L_KV, L_KV, MKV, D_Q,
        (long)L_Q * L_KV, (long)L_KV, (long)L_Q * D_Q);

    // 6) Output projection: ctxh[16384,512] @ woT^T + bo -> fp32 out.
    gemm_h<false, false><<<dim3(D_Q / HBM, MKV / HBM, 1), 256, SMEM_BYTES>>>(
        ctxh, woT, out, bo, MKV, D_Q, D_Q, D_Q, D_Q, D_Q, 0, 0, 0);
}

// round 8
// speedup vs baseline: 4.9202x; 1.1281x over previous
#include <cuda_runtime.h>
#include <cuda_fp16.h>
#include <cstdint>

// ---------------------------------------------------------------------------
// CrossAttention via fp16 mma.sync.m16n8k16 (fp32 accumulate) NT GEMMs.
// Round 8: 128x256x64 CTA tile, 64x64 warp tile, 3-stage cp.async pipeline,
// fp16 scores end-to-end (softmax half in/out, in place).
// ---------------------------------------------------------------------------

#define BATCH 8
#define L_Q   2048
#define L_KV  2048
#define D_Q   512
#define D_C   768
#define MKV   (BATCH * L_KV)   // 16384

// Scratch (device globals).
__device__ __align__(128) __half g_keyh [MKV * D_C];
__device__ __align__(128) __half g_valh [MKV * D_C];
__device__ __align__(128) __half g_qh   [BATCH * L_Q * D_Q];
__device__ __align__(128) __half g_wkT  [D_Q * D_C];
__device__ __align__(128) __half g_wvT  [D_Q * D_C];
__device__ __align__(128) __half g_woT  [D_Q * D_Q];
__device__ __align__(128) __half g_kproj[MKV * D_Q];
__device__ __align__(128) __half g_vprT [D_Q * MKV];              // [Dq][B*Lkv]
__device__ __align__(128) __half g_sc   [(size_t)BATCH * L_Q * L_KV]; // scores/probs
__device__ __align__(128) __half g_ctxh [BATCH * L_Q * D_Q];

// ---------------------------------------------------------------------------
// PTX helpers
// ---------------------------------------------------------------------------
__device__ __forceinline__ uint32_t smem_u32(const void* p) {
    uint32_t a;
    asm("{ .reg .u64 t; cvta.to.shared.u64 t, %1; cvt.u32.u64 %0, t; }"
        : "=r"(a) : "l"(p));
    return a;
}
__device__ __forceinline__ void cp16(uint32_t s, const void* g) {
    asm volatile("cp.async.cg.shared.global [%0], [%1], 16;" :: "r"(s), "l"(g));
}
#define CP_COMMIT()  asm volatile("cp.async.commit_group;")
#define CP_WAIT(n)   asm volatile("cp.async.wait_group %0;" :: "n"(n))

__device__ __forceinline__ void ldsm_x4(uint32_t r[4], uint32_t addr) {
    asm volatile("ldmatrix.sync.aligned.m8n8.x4.shared.b16 {%0,%1,%2,%3}, [%4];"
                 : "=r"(r[0]), "=r"(r[1]), "=r"(r[2]), "=r"(r[3]) : "r"(addr));
}
__device__ __forceinline__ void mma_f16(float c[4], const uint32_t a[4],
                                        uint32_t b0, uint32_t b1) {
    asm volatile(
        "mma.sync.aligned.m16n8k16.row.col.f32.f16.f16.f32 "
        "{%0,%1,%2,%3}, {%4,%5,%6,%7}, {%8,%9}, {%0,%1,%2,%3};"
        : "+f"(c[0]), "+f"(c[1]), "+f"(c[2]), "+f"(c[3])
        : "r"(a[0]), "r"(a[1]), "r"(a[2]), "r"(a[3]), "r"(b0), "r"(b1));
}

// ---------------------------------------------------------------------------
// fp16 NT GEMM: C[M,N] = A[M,K] @ B[N,K]^T (+ bias).
// BM=128, BN=256, BK=64. 256 threads (8 warps 2x4), warp tile 64x64.
// Smem rows: 64 halves + 8 pad = 144B (ldmatrix conflict-free: 8 consecutive
// rows hit 32 distinct banks). 3-stage cp.async pipeline.
// OUT_HALF: write __half2; else fp32 float2.
// ROWBIAS: bias indexed by m-row (transposed-output GEMM); else by n-col.
// Requires M%128==0, N%256==0, K%64==0, K/64 >= 2.
// ---------------------------------------------------------------------------
#define HBM 128
#define HBN 256
#define HBK 64
#define ROWB 144                       // bytes per smem row (72 halves)
#define STG_A (128 * ROWB)             // 18432
#define STG_B (256 * ROWB)             // 36864
#define STG   (STG_A + STG_B)          // 55296
#define NSTAGE 3
#define SMEM_BYTES (NSTAGE * STG)      // 165888

template <bool OUT_HALF, bool ROWBIAS>
__global__ void __launch_bounds__(256, 1)
gemm_h(const __half* __restrict__ A, const __half* __restrict__ B,
       void* __restrict__ Cv, const float* __restrict__ bias,
       int M, int N, int K, int ldA, int ldB, int ldC,
       long sA, long sB, long sC)
{
    extern __shared__ char smem[];
    const uint32_t sbase = smem_u32(smem);

    const int tid  = threadIdx.x;
    const int lane = tid & 31;
    const int warp = tid >> 5;
    const int g = lane >> 2;            // 0..7
    const int t = lane & 3;             // 0..3
    const int mw = (warp >> 2) * 64;    // warp M offset (0,64)
    const int nw = (warp & 3) * 64;     // warp N offset (0,64,128,192)

    const int bm = blockIdx.y * HBM;
    const int bn = blockIdx.x * HBN;
    A += (long)blockIdx.z * sA;
    B += (long)blockIdx.z * sB;

    // Loader: 16B chunks, 8 per row. A: 1024 chunks (4/thr), B: 2048 (8/thr).
    const int cu = tid & 7;             // chunk in row
    const int r0 = tid >> 3;            // 0..31

    const int nk = K / HBK;

    auto load_tile = [&](int kt) {
        const int s = kt % NSTAGE;
        const uint32_t as = sbase + s * STG;
        const uint32_t bs = as + STG_A;
        const long kof = (long)kt * HBK + cu * 8;
        #pragma unroll
        for (int i = 0; i < 4; i++) {
            const int r = r0 + 32 * i;
            cp16(as + r * ROWB + cu * 16, A + (long)(bm + r) * ldA + kof);
        }
        #pragma unroll
        for (int i = 0; i < 8; i++) {
            const int r = r0 + 32 * i;
            cp16(bs + r * ROWB + cu * 16, B + (long)(bn + r) * ldB + kof);
        }
        CP_COMMIT();
    };

    float acc[4][8][4];
    #pragma unroll
    for (int i = 0; i < 4; i++)
        #pragma unroll
        for (int j = 0; j < 8; j++)
            #pragma unroll
            for (int r = 0; r < 4; r++) acc[i][j][r] = 0.0f;

    load_tile(0);
    load_tile(1);

    // ldmatrix per-lane base offsets.
    const int lrow = lane & 15;
    const int lkb  = (lane >> 4) * 16;
    uint32_t aoff[4], boff[4];
    #pragma unroll
    for (int i = 0; i < 4; i++)  aoff[i]  = (mw + 16 * i + lrow) * ROWB + lkb;
    #pragma unroll
    for (int jj = 0; jj < 4; jj++) boff[jj] = (nw + 16 * jj + lrow) * ROWB + lkb;

    for (int kt = 0; kt < nk; kt++) {
        CP_WAIT(1);
        __syncthreads();                 // stage kt ready; all warps done with kt-1
        if (kt + 2 < nk) load_tile(kt + 2);

        const int s = kt % NSTAGE;
        const uint32_t as = sbase + s * STG;
        const uint32_t bs = as + STG_A;

        #pragma unroll
        for (int kh = 0; kh < 4; kh++) {          // 4 x k16
            uint32_t a[4][4], b[4][4];
            #pragma unroll
            for (int i = 0; i < 4; i++)  ldsm_x4(a[i], as + aoff[i] + kh * 32);
            #pragma unroll
            for (int jj = 0; jj < 4; jj++) ldsm_x4(b[jj], bs + boff[jj] + kh * 32);
            #pragma unroll
            for (int i = 0; i < 4; i++) {
                #pragma unroll
                for (int jj = 0; jj < 4; jj++) {
                    mma_f16(acc[i][2 * jj + 0], a[i], b[jj][0], b[jj][2]);
                    mma_f16(acc[i][2 * jj + 1], a[i], b[jj][1], b[jj][3]);
                }
            }
        }
    }

    // ----- epilogue -----
    #pragma unroll
    for (int i = 0; i < 4; i++) {
        const int r = bm + mw + 16 * i + g;
        float brow0 = 0.0f, brow1 = 0.0f;
        if (ROWBIAS && bias) { brow0 = bias[r]; brow1 = bias[r + 8]; }
        #pragma unroll
        for (int j = 0; j < 8; j++) {
            const int c = bn + nw + 8 * j + 2 * t;
            float bc0 = 0.0f, bc1 = 0.0f;
            if (!ROWBIAS && bias) { bc0 = bias[c]; bc1 = bias[c + 1]; }
            const float v00 = acc[i][j][0] + (ROWBIAS ? brow0 : bc0);
            const float v01 = acc[i][j][1] + (ROWBIAS ? brow0 : bc1);
            const float v10 = acc[i][j][2] + (ROWBIAS ? brow1 : bc0);
            const float v11 = acc[i][j][3] + (ROWBIAS ? brow1 : bc1);
            if (OUT_HALF) {
                __half* C = (__half*)Cv + (long)blockIdx.z * sC;
                *(__half2*)(C + (long)r * ldC + c)       = __floats2half2_rn(v00, v01);
                *(__half2*)(C + (long)(r + 8) * ldC + c) = __floats2half2_rn(v10, v11);
            } else {
                float* C = (float*)Cv + (long)blockIdx.z * sC;
                *(float2*)(C + (long)r * ldC + c)       = make_float2(v00, v01);
                *(float2*)(C + (long)(r + 8) * ldC + c) = make_float2(v10, v11);
            }
        }
    }
}

// ---------------------------------------------------------------------------
// fp32 -> fp16 convert (optionally scaled). n8 = n/8.
// ---------------------------------------------------------------------------
__global__ void __launch_bounds__(256)
f32_to_f16(__half* __restrict__ dst, const float* __restrict__ src,
           int n8, float scale)
{
    for (int i = blockIdx.x * blockDim.x + threadIdx.x; i < n8;
         i += gridDim.x * blockDim.x) {
        float4 v0 = ((const float4*)src)[2 * i];
        float4 v1 = ((const float4*)src)[2 * i + 1];
        __half2 h[4];
        h[0] = __floats2half2_rn(v0.x * scale, v0.y * scale);
        h[1] = __floats2half2_rn(v0.z * scale, v0.w * scale);
        h[2] = __floats2half2_rn(v1.x * scale, v1.y * scale);
        h[3] = __floats2half2_rn(v1.z * scale, v1.w * scale);
        ((uint4*)dst)[i] = *(uint4*)h;
    }
}

// ---------------------------------------------------------------------------
// Weight transpose + convert: dst_h[N,K] = (half)src[K,N].  K,N % 32 == 0.
// ---------------------------------------------------------------------------
__global__ void __launch_bounds__(256)
transpose_h(__half* __restrict__ dst, const float* __restrict__ src, int K, int N)
{
    __shared__ float tile[32][33];
    const int n0 = blockIdx.x * 32;
    const int k0 = blockIdx.y * 32;
    const int tx = threadIdx.x & 31;
    const int ty = threadIdx.x >> 5;
    #pragma unroll
    for (int i = 0; i < 32; i += 8)
        tile[ty + i][tx] = src[(long)(k0 + ty + i) * N + n0 + tx];
    __syncthreads();
    #pragma unroll
    for (int i = 0; i < 32; i += 8)
        dst[(long)(n0 + ty + i) * K + k0 + tx] = __float2half(tile[tx][ty + i]);
}

// ---------------------------------------------------------------------------
// In-place row softmax over 2048-length rows, fp16 in / fp16 out.
// ---------------------------------------------------------------------------
__global__ void __launch_bounds__(256)
softmax_h2048(__half* __restrict__ S)
{
    __half2* p = (__half2*)(S + (size_t)blockIdx.x * 2048);   // 1024 half2
    const int t = threadIdx.x;

    float v[8];
    #pragma unroll
    for (int i = 0; i < 4; i++) {
        float2 f = __half22float2(p[t + i * 256]);
        v[2 * i] = f.x; v[2 * i + 1] = f.y;
    }
    float mx = -1e30f;
    #pragma unroll
    for (int i = 0; i < 8; i++) mx = fmaxf(mx, v[i]);

    __shared__ float red[8];
    #pragma unroll
    for (int o = 16; o > 0; o >>= 1)
        mx = fmaxf(mx, __shfl_xor_sync(0xFFFFFFFFu, mx, o));
    if ((t & 31) == 0) red[t >> 5] = mx;
    __syncthreads();
    float rowmax = red[0];
    #pragma unroll
    for (int w = 1; w < 8; w++) rowmax = fmaxf(rowmax, red[w]);
    __syncthreads();

    float sum = 0.0f;
    #pragma unroll
    for (int i = 0; i < 8; i++) {
        v[i] = __expf(v[i] - rowmax);
        sum += v[i];
    }
    #pragma unroll
    for (int o = 16; o > 0; o >>= 1)
        sum += __shfl_xor_sync(0xFFFFFFFFu, sum, o);
    if ((t & 31) == 0) red[t >> 5] = sum;
    __syncthreads();
    float rowsum = 0.0f;
    #pragma unroll
    for (int w = 0; w < 8; w++) rowsum += red[w];

    const float inv = 1.0f / rowsum;
    #pragma unroll
    for (int i = 0; i < 4; i++)
        p[t + i * 256] = __floats2half2_rn(v[2 * i] * inv, v[2 * i + 1] * inv);
}

// ---------------------------------------------------------------------------
// Launcher
// ---------------------------------------------------------------------------
extern "C" void kernel_launch(void* const* d_in, const int* in_sizes, int n_in,
                              void* d_out, int out_size)
{
    const float* query = (const float*)d_in[0];
    const float* key   = (const float*)d_in[1];
    const float* value = (const float*)d_in[2];
    const float* Wk    = (const float*)d_in[3];
    const float* bk    = (const float*)d_in[4];
    const float* Wv    = (const float*)d_in[5];
    const float* bv    = (const float*)d_in[6];
    const float* Wo    = (const float*)d_in[7];
    const float* bo    = (const float*)d_in[8];
    float* out = (float*)d_out;

    __half *keyh, *valh, *qh, *wkT, *wvT, *woT, *kproj, *vprT, *sc, *ctxh;
    cudaGetSymbolAddress((void**)&keyh,  g_keyh);
    cudaGetSymbolAddress((void**)&valh,  g_valh);
    cudaGetSymbolAddress((void**)&qh,    g_qh);
    cudaGetSymbolAddress((void**)&wkT,   g_wkT);
    cudaGetSymbolAddress((void**)&wvT,   g_wvT);
    cudaGetSymbolAddress((void**)&woT,   g_woT);
    cudaGetSymbolAddress((void**)&kproj, g_kproj);
    cudaGetSymbolAddress((void**)&vprT,  g_vprT);
    cudaGetSymbolAddress((void**)&sc,    g_sc);
    cudaGetSymbolAddress((void**)&ctxh,  g_ctxh);

    static bool attr_done = false;
    if (!attr_done) {
        cudaFuncSetAttribute(gemm_h<true, false>,
                             cudaFuncAttributeMaxDynamicSharedMemorySize, SMEM_BYTES);
        cudaFuncSetAttribute(gemm_h<true, true>,
                             cudaFuncAttributeMaxDynamicSharedMemorySize, SMEM_BYTES);
        cudaFuncSetAttribute(gemm_h<false, false>,
                             cudaFuncAttributeMaxDynamicSharedMemorySize, SMEM_BYTES);
        attr_done = true;
    }

    const float scale = 1.0f / sqrtf((float)D_Q);

    // 0) fp16 conversions (scale folded into Q).
    f32_to_f16<<<512, 256>>>(keyh, key,   MKV * D_C / 8, 1.0f);
    f32_to_f16<<<512, 256>>>(valh, value, MKV * D_C / 8, 1.0f);
    f32_to_f16<<<512, 256>>>(qh,   query, BATCH * L_Q * D_Q / 8, scale);
    transpose_h<<<dim3(D_Q / 32, D_C / 32), 256>>>(wkT, Wk, D_C, D_Q);
    transpose_h<<<dim3(D_Q / 32, D_C / 32), 256>>>(wvT, Wv, D_C, D_Q);
    transpose_h<<<dim3(D_Q / 32, D_Q / 32), 256>>>(woT, Wo, D_Q, D_Q);

    // 1) K projection: kproj[16384,512] = keyh @ wkT^T + bk (col bias), half out.
    gemm_h<true, false><<<dim3(D_Q / HBN, MKV / HBM, 1), 256, SMEM_BYTES>>>(
        keyh, wkT, kproj, bk, MKV, D_Q, D_C, D_C, D_C, D_Q, 0, 0, 0);

    // 2) V projection TRANSPOSED: vprT[512,16384] = wvT @ valh^T + bv (ROW bias).
    gemm_h<true, true><<<dim3(MKV / HBN, D_Q / HBM, 1), 256, SMEM_BYTES>>>(
        wvT, valh, vprT, bv, D_Q, MKV, D_C, D_C, D_C, MKV, 0, 0, 0);

    // 3) Scores per batch: qh_b[2048,512] @ kproj_b^T -> fp16 (scale pre-folded).
    gemm_h<true, false><<<dim3(L_KV / HBN, L_Q / HBM, BATCH), 256, SMEM_BYTES>>>(
        qh, kproj, sc, nullptr, L_Q, L_KV, D_Q, D_Q, D_Q, L_KV,
        (long)L_Q * D_Q, (long)L_KV * D_Q, (long)L_Q * L_KV);

    // 4) Softmax in place (fp16).
    softmax_h2048<<<BATCH * L_Q, 256>>>(sc);

    // 5) Context per batch: probs_b[2048,2048] @ (vprT[:, b])^T -> ctxh, half out.
    gemm_h<true, false><<<dim3(D_Q / HBN, L_Q / HBM, BATCH), 256, SMEM_BYTES>>>(
        sc, vprT, ctxh, nullptr, L_Q, D_Q, L_KV, L_KV, MKV, D_Q,
        (long)L_Q * L_KV, (long)L_KV, (long)L_Q * D_Q);

    // 6) Output projection: ctxh[16384,512] @ woT^T + bo -> fp32 out.
    gemm_h<false, false><<<dim3(D_Q / HBN, MKV / HBM, 1), 256, SMEM_BYTES>>>(
        ctxh, woT, out, bo, MKV, D_Q, D_Q, D_Q, D_Q, D_Q, 0, 0, 0);
}

// round 10
// speedup vs baseline: 5.0677x; 1.0300x over previous
#include <cuda_runtime.h>
#include <cuda_fp16.h>
#include <cstdint>

// ---------------------------------------------------------------------------
// CrossAttention via fp16 mma.sync.m16n8k16 (fp32 accumulate) NT GEMMs.
// Round 9: kh-level fragment double-buffering, merged prep kernels.
// ---------------------------------------------------------------------------

#define BATCH 8
#define L_Q   2048
#define L_KV  2048
#define D_Q   512
#define D_C   768
#define MKV   (BATCH * L_KV)   // 16384

// Scratch (device globals).
__device__ __align__(128) __half g_keyh [MKV * D_C];
__device__ __align__(128) __half g_valh [MKV * D_C];
__device__ __align__(128) __half g_qh   [BATCH * L_Q * D_Q];
__device__ __align__(128) __half g_wkT  [D_Q * D_C];
__device__ __align__(128) __half g_wvT  [D_Q * D_C];
__device__ __align__(128) __half g_woT  [D_Q * D_Q];
__device__ __align__(128) __half g_kproj[MKV * D_Q];
__device__ __align__(128) __half g_vprT [D_Q * MKV];              // [Dq][B*Lkv]
__device__ __align__(128) __half g_sc   [(size_t)BATCH * L_Q * L_KV]; // scores/probs
__device__ __align__(128) __half g_ctxh [BATCH * L_Q * D_Q];

// ---------------------------------------------------------------------------
// PTX helpers
// ---------------------------------------------------------------------------
__device__ __forceinline__ uint32_t smem_u32(const void* p) {
    uint32_t a;
    asm("{ .reg .u64 t; cvta.to.shared.u64 t, %1; cvt.u32.u64 %0, t; }"
        : "=r"(a) : "l"(p));
    return a;
}
__device__ __forceinline__ void cp16(uint32_t s, const void* g) {
    asm volatile("cp.async.cg.shared.global [%0], [%1], 16;" :: "r"(s), "l"(g));
}
#define CP_COMMIT()  asm volatile("cp.async.commit_group;")
#define CP_WAIT(n)   asm volatile("cp.async.wait_group %0;" :: "n"(n))

__device__ __forceinline__ void ldsm_x4(uint32_t r[4], uint32_t addr) {
    asm volatile("ldmatrix.sync.aligned.m8n8.x4.shared.b16 {%0,%1,%2,%3}, [%4];"
                 : "=r"(r[0]), "=r"(r[1]), "=r"(r[2]), "=r"(r[3]) : "r"(addr));
}
__device__ __forceinline__ void mma_f16(float c[4], const uint32_t a[4],
                                        uint32_t b0, uint32_t b1) {
    asm volatile(
        "mma.sync.aligned.m16n8k16.row.col.f32.f16.f16.f32 "
        "{%0,%1,%2,%3}, {%4,%5,%6,%7}, {%8,%9}, {%0,%1,%2,%3};"
        : "+f"(c[0]), "+f"(c[1]), "+f"(c[2]), "+f"(c[3])
        : "r"(a[0]), "r"(a[1]), "r"(a[2]), "r"(a[3]), "r"(b0), "r"(b1));
}

// ---------------------------------------------------------------------------
// fp16 NT GEMM: C[M,N] = A[M,K] @ B[N,K]^T (+ bias).
// BM=128, BN=256, BK=64. 256 threads (8 warps 2x4), warp tile 64x64.
// Smem rows: 64 halves + 8 pad = 144B. 3-stage cp.async pipeline.
// kh-level fragment double buffering (ldsm for kh+1 issued during kh's MMAs).
// ---------------------------------------------------------------------------
#define HBM 128
#define HBN 256
#define HBK 64
#define ROWB 144
#define STG_A (128 * ROWB)             // 18432
#define STG_B (256 * ROWB)             // 36864
#define STG   (STG_A + STG_B)          // 55296
#define NSTAGE 3
#define SMEM_BYTES (NSTAGE * STG)      // 165888

template <bool OUT_HALF, bool ROWBIAS>
__global__ void __launch_bounds__(256, 1)
gemm_h(const __half* __restrict__ A, const __half* __restrict__ B,
       void* __restrict__ Cv, const float* __restrict__ bias,
       int M, int N, int K, int ldA, int ldB, int ldC,
       long sA, long sB, long sC)
{
    extern __shared__ char smem[];
    const uint32_t sbase = smem_u32(smem);

    const int tid  = threadIdx.x;
    const int lane = tid & 31;
    const int warp = tid >> 5;
    const int g = lane >> 2;
    const int t = lane & 3;
    const int mw = (warp >> 2) * 64;
    const int nw = (warp & 3) * 64;

    const int bm = blockIdx.y * HBM;
    const int bn = blockIdx.x * HBN;
    A += (long)blockIdx.z * sA;
    B += (long)blockIdx.z * sB;

    const int cu = tid & 7;
    const int r0 = tid >> 3;

    const int nk = K / HBK;

    auto load_tile = [&](int kt) {
        const int s = kt % NSTAGE;
        const uint32_t as = sbase + s * STG;
        const uint32_t bs = as + STG_A;
        const long kof = (long)kt * HBK + cu * 8;
        #pragma unroll
        for (int i = 0; i < 4; i++) {
            const int r = r0 + 32 * i;
            cp16(as + r * ROWB + cu * 16, A + (long)(bm + r) * ldA + kof);
        }
        #pragma unroll
        for (int i = 0; i < 8; i++) {
            const int r = r0 + 32 * i;
            cp16(bs + r * ROWB + cu * 16, B + (long)(bn + r) * ldB + kof);
        }
        CP_COMMIT();
    };

    float acc[4][8][4];
    #pragma unroll
    for (int i = 0; i < 4; i++)
        #pragma unroll
        for (int j = 0; j < 8; j++)
            #pragma unroll
            for (int r = 0; r < 4; r++) acc[i][j][r] = 0.0f;

    load_tile(0);
    load_tile(1);

    const int lrow = lane & 15;
    const int lkb  = (lane >> 4) * 16;
    uint32_t aoff[4], boff[4];
    #pragma unroll
    for (int i = 0; i < 4; i++)  aoff[i]  = (mw + 16 * i + lrow) * ROWB + lkb;
    #pragma unroll
    for (int jj = 0; jj < 4; jj++) boff[jj] = (nw + 16 * jj + lrow) * ROWB + lkb;

    uint32_t a[2][4][4], b[2][4][4];   // double-buffered fragments

    for (int kt = 0; kt < nk; kt++) {
        CP_WAIT(1);
        __syncthreads();
        if (kt + 2 < nk) load_tile(kt + 2);

        const int s = kt % NSTAGE;
        const uint32_t as = sbase + s * STG;
        const uint32_t bs = as + STG_A;

        // Prime kh=0 fragments.
        #pragma unroll
        for (int i = 0; i < 4; i++)  ldsm_x4(a[0][i], as + aoff[i]);
        #pragma unroll
        for (int jj = 0; jj < 4; jj++) ldsm_x4(b[0][jj], bs + boff[jj]);

        #pragma unroll
        for (int kh = 0; kh < 4; kh++) {
            const int cur = kh & 1, nxt = cur ^ 1;
            if (kh < 3) {   // prefetch kh+1 while MMAs of kh run
                #pragma unroll
                for (int i = 0; i < 4; i++)
                    ldsm_x4(a[nxt][i], as + aoff[i] + (kh + 1) * 32);
                #pragma unroll
                for (int jj = 0; jj < 4; jj++)
                    ldsm_x4(b[nxt][jj], bs + boff[jj] + (kh + 1) * 32);
            }
            #pragma unroll
            for (int i = 0; i < 4; i++) {
                #pragma unroll
                for (int jj = 0; jj < 4; jj++) {
                    mma_f16(acc[i][2 * jj + 0], a[cur][i], b[cur][jj][0], b[cur][jj][2]);
                    mma_f16(acc[i][2 * jj + 1], a[cur][i], b[cur][jj][1], b[cur][jj][3]);
                }
            }
        }
    }

    // ----- epilogue -----
    #pragma unroll
    for (int i = 0; i < 4; i++) {
        const int r = bm + mw + 16 * i + g;
        float brow0 = 0.0f, brow1 = 0.0f;
        if (ROWBIAS && bias) { brow0 = bias[r]; brow1 = bias[r + 8]; }
        #pragma unroll
        for (int j = 0; j < 8; j++) {
            const int c = bn + nw + 8 * j + 2 * t;
            float bc0 = 0.0f, bc1 = 0.0f;
            if (!ROWBIAS && bias) { bc0 = bias[c]; bc1 = bias[c + 1]; }
            const float v00 = acc[i][j][0] + (ROWBIAS ? brow0 : bc0);
            const float v01 = acc[i][j][1] + (ROWBIAS ? brow0 : bc1);
            const float v10 = acc[i][j][2] + (ROWBIAS ? brow1 : bc0);
            const float v11 = acc[i][j][3] + (ROWBIAS ? brow1 : bc1);
            if (OUT_HALF) {
                __half* C = (__half*)Cv + (long)blockIdx.z * sC;
                *(__half2*)(C + (long)r * ldC + c)       = __floats2half2_rn(v00, v01);
                *(__half2*)(C + (long)(r + 8) * ldC + c) = __floats2half2_rn(v10, v11);
            } else {
                float* C = (float*)Cv + (long)blockIdx.z * sC;
                *(float2*)(C + (long)r * ldC + c)       = make_float2(v00, v01);
                *(float2*)(C + (long)(r + 8) * ldC + c) = make_float2(v10, v11);
            }
        }
    }
}

// ---------------------------------------------------------------------------
// Merged conversion: key (n8k chunks), value (n8k), q (n8q, scaled).
// One grid-stride pass over the concatenated chunk range.
// ---------------------------------------------------------------------------
__global__ void __launch_bounds__(256)
prep_convert(__half* __restrict__ keyh, const float* __restrict__ key,
             __half* __restrict__ valh, const float* __restrict__ value,
             __half* __restrict__ qh,   const float* __restrict__ query,
             int n8k, int n8q, float qscale)
{
    const int total = 2 * n8k + n8q;
    for (int i = blockIdx.x * blockDim.x + threadIdx.x; i < total;
         i += gridDim.x * blockDim.x) {
        const float* src; __half* dst; int idx; float sc;
        if (i < n8k)            { src = key;   dst = keyh; idx = i;           sc = 1.0f; }
        else if (i < 2 * n8k)   { src = value; dst = valh; idx = i - n8k;     sc = 1.0f; }
        else                    { src = query; dst = qh;   idx = i - 2 * n8k; sc = qscale; }
        float4 v0 = ((const float4*)src)[2 * idx];
        float4 v1 = ((const float4*)src)[2 * idx + 1];
        __half2 h[4];
        h[0] = __floats2half2_rn(v0.x * sc, v0.y * sc);
        h[1] = __floats2half2_rn(v0.z * sc, v0.w * sc);
        h[2] = __floats2half2_rn(v1.x * sc, v1.y * sc);
        h[3] = __floats2half2_rn(v1.z * sc, v1.w * sc);
        ((uint4*)dst)[idx] = *(uint4*)h;
    }
}

// ---------------------------------------------------------------------------
// Merged weight transposes: Wk[768,512]->wkT, Wv[768,512]->wvT, Wo[512,512]->woT.
// Task by block range; 32x32 tiles.
// ---------------------------------------------------------------------------
__global__ void __launch_bounds__(256)
prep_transpose(__half* __restrict__ wkT, const float* __restrict__ Wk,
               __half* __restrict__ wvT, const float* __restrict__ Wv,
               __half* __restrict__ woT, const float* __restrict__ Wo)
{
    // Wk: 16x24=384 tile-blocks, Wv: 384, Wo: 16x16=256. Total 1024.
    int b = blockIdx.x;
    const float* src; __half* dst; int K, N;
    if (b < 384)       { src = Wk; dst = wkT; K = D_C; N = D_Q; }
    else if (b < 768)  { src = Wv; dst = wvT; K = D_C; N = D_Q; b -= 384; }
    else               { src = Wo; dst = woT; K = D_Q; N = D_Q; b -= 768; }
    const int ntx = N / 32;
    const int n0 = (b % ntx) * 32;
    const int k0 = (b / ntx) * 32;

    __shared__ float tile[32][33];
    const int tx = threadIdx.x & 31;
    const int ty = threadIdx.x >> 5;
    #pragma unroll
    for (int i = 0; i < 32; i += 8)
        tile[ty + i][tx] = src[(long)(k0 + ty + i) * N + n0 + tx];
    __syncthreads();
    #pragma unroll
    for (int i = 0; i < 32; i += 8)
        dst[(long)(n0 + ty + i) * K + k0 + tx] = __float2half(tile[tx][ty + i]);
}

// ---------------------------------------------------------------------------
// In-place row softmax over 2048-length rows, fp16 in / fp16 out.
// ---------------------------------------------------------------------------
__global__ void __launch_bounds__(256)
softmax_h2048(__half* __restrict__ S)
{
    __half2* p = (__half2*)(S + (size_t)blockIdx.x * 2048);
    const int t = threadIdx.x;

    float v[8];
    #pragma unroll
    for (int i = 0; i < 4; i++) {
        float2 f = __half22float2(p[t + i * 256]);
        v[2 * i] = f.x; v[2 * i + 1] = f.y;
    }
    float mx = -1e30f;
    #pragma unroll
    for (int i = 0; i < 8; i++) mx = fmaxf(mx, v[i]);

    __shared__ float red[8];
    #pragma unroll
    for (int o = 16; o > 0; o >>= 1)
        mx = fmaxf(mx, __shfl_xor_sync(0xFFFFFFFFu, mx, o));
    if ((t & 31) == 0) red[t >> 5] = mx;
    __syncthreads();
    float rowmax = red[0];
    #pragma unroll
    for (int w = 1; w < 8; w++) rowmax = fmaxf(rowmax, red[w]);
    __syncthreads();

    float sum = 0.0f;
    #pragma unroll
    for (int i = 0; i < 8; i++) {
        v[i] = __expf(v[i] - rowmax);
        sum += v[i];
    }
    #pragma unroll
    for (int o = 16; o > 0; o >>= 1)
        sum += __shfl_xor_sync(0xFFFFFFFFu, sum, o);
    if ((t & 31) == 0) red[t >> 5] = sum;
    __syncthreads();
    float rowsum = 0.0f;
    #pragma unroll
    for (int w = 0; w < 8; w++) rowsum += red[w];

    const float inv = 1.0f / rowsum;
    #pragma unroll
    for (int i = 0; i < 4; i++)
        p[t + i * 256] = __floats2half2_rn(v[2 * i] * inv, v[2 * i + 1] * inv);
}

// ---------------------------------------------------------------------------
// Launcher
// ---------------------------------------------------------------------------
extern "C" void kernel_launch(void* const* d_in, const int* in_sizes, int n_in,
                              void* d_out, int out_size)
{
    const float* query = (const float*)d_in[0];
    const float* key   = (const float*)d_in[1];
    const float* value = (const float*)d_in[2];
    const float* Wk    = (const float*)d_in[3];
    const float* bk    = (const float*)d_in[4];
    const float* Wv    = (const float*)d_in[5];
    const float* bv    = (const float*)d_in[6];
    const float* Wo    = (const float*)d_in[7];
    const float* bo    = (const float*)d_in[8];
    float* out = (float*)d_out;

    __half *keyh, *valh, *qh, *wkT, *wvT, *woT, *kproj, *vprT, *sc, *ctxh;
    cudaGetSymbolAddress((void**)&keyh,  g_keyh);
    cudaGetSymbolAddress((void**)&valh,  g_valh);
    cudaGetSymbolAddress((void**)&qh,    g_qh);
    cudaGetSymbolAddress((void**)&wkT,   g_wkT);
    cudaGetSymbolAddress((void**)&wvT,   g_wvT);
    cudaGetSymbolAddress((void**)&woT,   g_woT);
    cudaGetSymbolAddress((void**)&kproj, g_kproj);
    cudaGetSymbolAddress((void**)&vprT,  g_vprT);
    cudaGetSymbolAddress((void**)&sc,    g_sc);
    cudaGetSymbolAddress((void**)&ctxh,  g_ctxh);

    static bool attr_done = false;
    if (!attr_done) {
        cudaFuncSetAttribute(gemm_h<true, false>,
                             cudaFuncAttributeMaxDynamicSharedMemorySize, SMEM_BYTES);
        cudaFuncSetAttribute(gemm_h<true, true>,
                             cudaFuncAttributeMaxDynamicSharedMemorySize, SMEM_BYTES);
        cudaFuncSetAttribute(gemm_h<false, false>,
                             cudaFuncAttributeMaxDynamicSharedMemorySize, SMEM_BYTES);
        attr_done = true;
    }

    const float scale = 1.0f / sqrtf((float)D_Q);

    // 0) merged prep: conversions (scale folded into Q) + weight transposes.
    prep_convert<<<2048, 256>>>(keyh, key, valh, value, qh, query,
                                MKV * D_C / 8, BATCH * L_Q * D_Q / 8, scale);
    prep_transpose<<<1024, 256>>>(wkT, Wk, wvT, Wv, woT, Wo);

    // 1) K projection: kproj[16384,512] = keyh @ wkT^T + bk (col bias), half out.
    gemm_h<true, false><<<dim3(D_Q / HBN, MKV / HBM, 1), 256, SMEM_BYTES>>>(
        keyh, wkT, kproj, bk, MKV, D_Q, D_C, D_C, D_C, D_Q, 0, 0, 0);

    // 2) V projection TRANSPOSED: vprT[512,16384] = wvT @ valh^T + bv (ROW bias).
    gemm_h<true, true><<<dim3(MKV / HBN, D_Q / HBM, 1), 256, SMEM_BYTES>>>(
        wvT, valh, vprT, bv, D_Q, MKV, D_C, D_C, D_C, MKV, 0, 0, 0);

    // 3) Scores per batch: qh_b[2048,512] @ kproj_b^T -> fp16 (scale pre-folded).
    gemm_h<true, false><<<dim3(L_KV / HBN, L_Q / HBM, BATCH), 256, SMEM_BYTES>>>(
        qh, kproj, sc, nullptr, L_Q, L_KV, D_Q, D_Q, D_Q, L_KV,
        (long)L_Q * D_Q, (long)L_KV * D_Q, (long)L_Q * L_KV);

    // 4) Softmax in place (fp16).
    softmax_h2048<<<BATCH * L_Q, 256>>>(sc);

    // 5) Context per batch: probs_b[2048,2048] @ (vprT[:, b])^T -> ctxh, half out.
    gemm_h<true, false><<<dim3(D_Q / HBN, L_Q / HBM, BATCH), 256, SMEM_BYTES>>>(
        sc, vprT, ctxh, nullptr, L_Q, D_Q, L_KV, L_KV, MKV, D_Q,
        (long)L_Q * L_KV, (long)L_KV, (long)L_Q * D_Q);

    // 6) Output projection: ctxh[16384,512] @ woT^T + bo -> fp32 out.
    gemm_h<false, false><<<dim3(D_Q / HBN, MKV / HBM, 1), 256, SMEM_BYTES>>>(
        ctxh, woT, out, bo, MKV, D_Q, D_Q, D_Q, D_Q, D_Q, 0, 0, 0);
}

// round 11
// speedup vs baseline: 5.0976x; 1.0059x over previous
#include <cuda_runtime.h>
#include <cuda_fp16.h>
#include <cstdint>

// ---------------------------------------------------------------------------
// CrossAttention via fp16 mma.sync.m16n8k16 (fp32 accumulate) NT GEMMs.
// Round 11: BK=128 / NSTAGE=2 (204KB smem) to halve per-stage sync overhead.
// ---------------------------------------------------------------------------

#define BATCH 8
#define L_Q   2048
#define L_KV  2048
#define D_Q   512
#define D_C   768
#define MKV   (BATCH * L_KV)   // 16384

// Scratch (device globals).
__device__ __align__(128) __half g_keyh [MKV * D_C];
__device__ __align__(128) __half g_valh [MKV * D_C];
__device__ __align__(128) __half g_qh   [BATCH * L_Q * D_Q];
__device__ __align__(128) __half g_wkT  [D_Q * D_C];
__device__ __align__(128) __half g_wvT  [D_Q * D_C];
__device__ __align__(128) __half g_woT  [D_Q * D_Q];
__device__ __align__(128) __half g_kproj[MKV * D_Q];
__device__ __align__(128) __half g_vprT [D_Q * MKV];              // [Dq][B*Lkv]
__device__ __align__(128) __half g_sc   [(size_t)BATCH * L_Q * L_KV]; // scores/probs
__device__ __align__(128) __half g_ctxh [BATCH * L_Q * D_Q];

// ---------------------------------------------------------------------------
// PTX helpers
// ---------------------------------------------------------------------------
__device__ __forceinline__ uint32_t smem_u32(const void* p) {
    uint32_t a;
    asm("{ .reg .u64 t; cvta.to.shared.u64 t, %1; cvt.u32.u64 %0, t; }"
        : "=r"(a) : "l"(p));
    return a;
}
__device__ __forceinline__ void cp16(uint32_t s, const void* g) {
    asm volatile("cp.async.cg.shared.global [%0], [%1], 16;" :: "r"(s), "l"(g));
}
#define CP_COMMIT()  asm volatile("cp.async.commit_group;")
#define CP_WAIT(n)   asm volatile("cp.async.wait_group %0;" :: "n"(n))

__device__ __forceinline__ void ldsm_x4(uint32_t r[4], uint32_t addr) {
    asm volatile("ldmatrix.sync.aligned.m8n8.x4.shared.b16 {%0,%1,%2,%3}, [%4];"
                 : "=r"(r[0]), "=r"(r[1]), "=r"(r[2]), "=r"(r[3]) : "r"(addr));
}
__device__ __forceinline__ void mma_f16(float c[4], const uint32_t a[4],
                                        uint32_t b0, uint32_t b1) {
    asm volatile(
        "mma.sync.aligned.m16n8k16.row.col.f32.f16.f16.f32 "
        "{%0,%1,%2,%3}, {%4,%5,%6,%7}, {%8,%9}, {%0,%1,%2,%3};"
        : "+f"(c[0]), "+f"(c[1]), "+f"(c[2]), "+f"(c[3])
        : "r"(a[0]), "r"(a[1]), "r"(a[2]), "r"(a[3]), "r"(b0), "r"(b1));
}

// ---------------------------------------------------------------------------
// fp16 NT GEMM: C[M,N] = A[M,K] @ B[N,K]^T (+ bias).
// BM=128, BN=256, BK=128. 256 threads (8 warps 2x4), warp tile 64x64.
// Smem rows: 128 halves + 8 pad = 272B (68 words = 4 mod 32: same
// conflict-free ldsm/cp.async bank mapping as the 144B layout).
// 2-stage cp.async pipeline (204KB smem); fragment double-buffering over
// 8 k16-steps per stage. Requires M%128==0, N%256==0, K%128==0, K/128>=2.
// ---------------------------------------------------------------------------
#define HBM 128
#define HBN 256
#define HBK 128
#define ROWB 272                       // bytes per smem row (136 halves)
#define STG_A (128 * ROWB)             // 34816
#define STG_B (256 * ROWB)             // 69632
#define STG   (STG_A + STG_B)          // 104448
#define NSTAGE 2
#define SMEM_BYTES (NSTAGE * STG)      // 208896

template <bool OUT_HALF, bool ROWBIAS>
__global__ void __launch_bounds__(256, 1)
gemm_h(const __half* __restrict__ A, const __half* __restrict__ B,
       void* __restrict__ Cv, const float* __restrict__ bias,
       int M, int N, int K, int ldA, int ldB, int ldC,
       long sA, long sB, long sC)
{
    extern __shared__ char smem[];
    const uint32_t sbase = smem_u32(smem);

    const int tid  = threadIdx.x;
    const int lane = tid & 31;
    const int warp = tid >> 5;
    const int g = lane >> 2;
    const int t = lane & 3;
    const int mw = (warp >> 2) * 64;
    const int nw = (warp & 3) * 64;

    const int bm = blockIdx.y * HBM;
    const int bn = blockIdx.x * HBN;
    A += (long)blockIdx.z * sA;
    B += (long)blockIdx.z * sB;

    // Loader: 16 x 16B chunks per 256B row. A: 2048 chunks (8/thr),
    // B: 4096 chunks (16/thr).
    const int cu = tid & 15;            // chunk in row
    const int r0 = tid >> 4;            // 0..15

    const int nk = K / HBK;

    auto load_tile = [&](int kt) {
        const int s = kt & 1;
        const uint32_t as = sbase + s * STG;
        const uint32_t bs = as + STG_A;
        const long kof = (long)kt * HBK + cu * 8;
        #pragma unroll
        for (int i = 0; i < 8; i++) {
            const int r = r0 + 16 * i;
            cp16(as + r * ROWB + cu * 16, A + (long)(bm + r) * ldA + kof);
        }
        #pragma unroll
        for (int i = 0; i < 16; i++) {
            const int r = r0 + 16 * i;
            cp16(bs + r * ROWB + cu * 16, B + (long)(bn + r) * ldB + kof);
        }
        CP_COMMIT();
    };

    float acc[4][8][4];
    #pragma unroll
    for (int i = 0; i < 4; i++)
        #pragma unroll
        for (int j = 0; j < 8; j++)
            #pragma unroll
            for (int r = 0; r < 4; r++) acc[i][j][r] = 0.0f;

    load_tile(0);

    const int lrow = lane & 15;
    const int lkb  = (lane >> 4) * 16;
    uint32_t aoff[4], boff[4];
    #pragma unroll
    for (int i = 0; i < 4; i++)  aoff[i]  = (mw + 16 * i + lrow) * ROWB + lkb;
    #pragma unroll
    for (int jj = 0; jj < 4; jj++) boff[jj] = (nw + 16 * jj + lrow) * ROWB + lkb;

    uint32_t a[2][4][4], b[2][4][4];   // double-buffered fragments

    for (int kt = 0; kt < nk; kt++) {
        if (kt + 1 < nk) { load_tile(kt + 1); CP_WAIT(1); }
        else             { CP_WAIT(0); }
        __syncthreads();                 // stage kt ready in buffer kt&1

        const int s = kt & 1;
        const uint32_t as = sbase + s * STG;
        const uint32_t bs = as + STG_A;

        // Prime kh=0 fragments.
        #pragma unroll
        for (int i = 0; i < 4; i++)  ldsm_x4(a[0][i], as + aoff[i]);
        #pragma unroll
        for (int jj = 0; jj < 4; jj++) ldsm_x4(b[0][jj], bs + boff[jj]);

        #pragma unroll
        for (int kh = 0; kh < 8; kh++) {        // 8 x k16 per stage
            const int cur = kh & 1, nxt = cur ^ 1;
            if (kh < 7) {   // prefetch kh+1 while MMAs of kh run
                #pragma unroll
                for (int i = 0; i < 4; i++)
                    ldsm_x4(a[nxt][i], as + aoff[i] + (kh + 1) * 32);
                #pragma unroll
                for (int jj = 0; jj < 4; jj++)
                    ldsm_x4(b[nxt][jj], bs + boff[jj] + (kh + 1) * 32);
            }
            #pragma unroll
            for (int i = 0; i < 4; i++) {
                #pragma unroll
                for (int jj = 0; jj < 4; jj++) {
                    mma_f16(acc[i][2 * jj + 0], a[cur][i], b[cur][jj][0], b[cur][jj][2]);
                    mma_f16(acc[i][2 * jj + 1], a[cur][i], b[cur][jj][1], b[cur][jj][3]);
                }
            }
        }
        __syncthreads();                 // all warps done with buffer kt&1
    }

    // ----- epilogue -----
    #pragma unroll
    for (int i = 0; i < 4; i++) {
        const int r = bm + mw + 16 * i + g;
        float brow0 = 0.0f, brow1 = 0.0f;
        if (ROWBIAS && bias) { brow0 = bias[r]; brow1 = bias[r + 8]; }
        #pragma unroll
        for (int j = 0; j < 8; j++) {
            const int c = bn + nw + 8 * j + 2 * t;
            float bc0 = 0.0f, bc1 = 0.0f;
            if (!ROWBIAS && bias) { bc0 = bias[c]; bc1 = bias[c + 1]; }
            const float v00 = acc[i][j][0] + (ROWBIAS ? brow0 : bc0);
            const float v01 = acc[i][j][1] + (ROWBIAS ? brow0 : bc1);
            const float v10 = acc[i][j][2] + (ROWBIAS ? brow1 : bc0);
            const float v11 = acc[i][j][3] + (ROWBIAS ? brow1 : bc1);
            if (OUT_HALF) {
                __half* C = (__half*)Cv + (long)blockIdx.z * sC;
                *(__half2*)(C + (long)r * ldC + c)       = __floats2half2_rn(v00, v01);
                *(__half2*)(C + (long)(r + 8) * ldC + c) = __floats2half2_rn(v10, v11);
            } else {
                float* C = (float*)Cv + (long)blockIdx.z * sC;
                *(float2*)(C + (long)r * ldC + c)       = make_float2(v00, v01);
                *(float2*)(C + (long)(r + 8) * ldC + c) = make_float2(v10, v11);
            }
        }
    }
}

// ---------------------------------------------------------------------------
// Merged conversion: key, value, q (scaled). Grid-stride over 16B chunks.
// ---------------------------------------------------------------------------
__global__ void __launch_bounds__(256)
prep_convert(__half* __restrict__ keyh, const float* __restrict__ key,
             __half* __restrict__ valh, const float* __restrict__ value,
             __half* __restrict__ qh,   const float* __restrict__ query,
             int n8k, int n8q, float qscale)
{
    const int total = 2 * n8k + n8q;
    for (int i = blockIdx.x * blockDim.x + threadIdx.x; i < total;
         i += gridDim.x * blockDim.x) {
        const float* src; __half* dst; int idx; float sc;
        if (i < n8k)            { src = key;   dst = keyh; idx = i;           sc = 1.0f; }
        else if (i < 2 * n8k)   { src = value; dst = valh; idx = i - n8k;     sc = 1.0f; }
        else                    { src = query; dst = qh;   idx = i - 2 * n8k; sc = qscale; }
        float4 v0 = ((const float4*)src)[2 * idx];
        float4 v1 = ((const float4*)src)[2 * idx + 1];
        __half2 h[4];
        h[0] = __floats2half2_rn(v0.x * sc, v0.y * sc);
        h[1] = __floats2half2_rn(v0.z * sc, v0.w * sc);
        h[2] = __floats2half2_rn(v1.x * sc, v1.y * sc);
        h[3] = __floats2half2_rn(v1.z * sc, v1.w * sc);
        ((uint4*)dst)[idx] = *(uint4*)h;
    }
}

// ---------------------------------------------------------------------------
// Merged weight transposes: Wk,Wv [768,512] and Wo [512,512] -> [N,K] fp16.
// ---------------------------------------------------------------------------
__global__ void __launch_bounds__(256)
prep_transpose(__half* __restrict__ wkT, const float* __restrict__ Wk,
               __half* __restrict__ wvT, const float* __restrict__ Wv,
               __half* __restrict__ woT, const float* __restrict__ Wo)
{
    int b = blockIdx.x;
    const float* src; __half* dst; int K, N;
    if (b < 384)       { src = Wk; dst = wkT; K = D_C; N = D_Q; }
    else if (b < 768)  { src = Wv; dst = wvT; K = D_C; N = D_Q; b -= 384; }
    else               { src = Wo; dst = woT; K = D_Q; N = D_Q; b -= 768; }
    const int ntx = N / 32;
    const int n0 = (b % ntx) * 32;
    const int k0 = (b / ntx) * 32;

    __shared__ float tile[32][33];
    const int tx = threadIdx.x & 31;
    const int ty = threadIdx.x >> 5;
    #pragma unroll
    for (int i = 0; i < 32; i += 8)
        tile[ty + i][tx] = src[(long)(k0 + ty + i) * N + n0 + tx];
    __syncthreads();
    #pragma unroll
    for (int i = 0; i < 32; i += 8)
        dst[(long)(n0 + ty + i) * K + k0 + tx] = __float2half(tile[tx][ty + i]);
}

// ---------------------------------------------------------------------------
// In-place row softmax over 2048-length rows, fp16 in / fp16 out.
// ---------------------------------------------------------------------------
__global__ void __launch_bounds__(256)
softmax_h2048(__half* __restrict__ S)
{
    __half2* p = (__half2*)(S + (size_t)blockIdx.x * 2048);
    const int t = threadIdx.x;

    float v[8];
    #pragma unroll
    for (int i = 0; i < 4; i++) {
        float2 f = __half22float2(p[t + i * 256]);
        v[2 * i] = f.x; v[2 * i + 1] = f.y;
    }
    float mx = -1e30f;
    #pragma unroll
    for (int i = 0; i < 8; i++) mx = fmaxf(mx, v[i]);

    __shared__ float red[8];
    #pragma unroll
    for (int o = 16; o > 0; o >>= 1)
        mx = fmaxf(mx, __shfl_xor_sync(0xFFFFFFFFu, mx, o));
    if ((t & 31) == 0) red[t >> 5] = mx;
    __syncthreads();
    float rowmax = red[0];
    #pragma unroll
    for (int w = 1; w < 8; w++) rowmax = fmaxf(rowmax, red[w]);
    __syncthreads();

    float sum = 0.0f;
    #pragma unroll
    for (int i = 0; i < 8; i++) {
        v[i] = __expf(v[i] - rowmax);
        sum += v[i];
    }
    #pragma unroll
    for (int o = 16; o > 0; o >>= 1)
        sum += __shfl_xor_sync(0xFFFFFFFFu, sum, o);
    if ((t & 31) == 0) red[t >> 5] = sum;
    __syncthreads();
    float rowsum = 0.0f;
    #pragma unroll
    for (int w = 0; w < 8; w++) rowsum += red[w];

    const float inv = 1.0f / rowsum;
    #pragma unroll
    for (int i = 0; i < 4; i++)
        p[t + i * 256] = __floats2half2_rn(v[2 * i] * inv, v[2 * i + 1] * inv);
}

// ---------------------------------------------------------------------------
// Launcher
// ---------------------------------------------------------------------------
extern "C" void kernel_launch(void* const* d_in, const int* in_sizes, int n_in,
                              void* d_out, int out_size)
{
    const float* query = (const float*)d_in[0];
    const float* key   = (const float*)d_in[1];
    const float* value = (const float*)d_in[2];
    const float* Wk    = (const float*)d_in[3];
    const float* bk    = (const float*)d_in[4];
    const float* Wv    = (const float*)d_in[5];
    const float* bv    = (const float*)d_in[6];
    const float* Wo    = (const float*)d_in[7];
    const float* bo    = (const float*)d_in[8];
    float* out = (float*)d_out;

    __half *keyh, *valh, *qh, *wkT, *wvT, *woT, *kproj, *vprT, *sc, *ctxh;
    cudaGetSymbolAddress((void**)&keyh,  g_keyh);
    cudaGetSymbolAddress((void**)&valh,  g_valh);
    cudaGetSymbolAddress((void**)&qh,    g_qh);
    cudaGetSymbolAddress((void**)&wkT,   g_wkT);
    cudaGetSymbolAddress((void**)&wvT,   g_wvT);
    cudaGetSymbolAddress((void**)&woT,   g_woT);
    cudaGetSymbolAddress((void**)&kproj, g_kproj);
    cudaGetSymbolAddress((void**)&vprT,  g_vprT);
    cudaGetSymbolAddress((void**)&sc,    g_sc);
    cudaGetSymbolAddress((void**)&ctxh,  g_ctxh);

    static bool attr_done = false;
    if (!attr_done) {
        cudaFuncSetAttribute(gemm_h<true, false>,
                             cudaFuncAttributeMaxDynamicSharedMemorySize, SMEM_BYTES);
        cudaFuncSetAttribute(gemm_h<true, true>,
                             cudaFuncAttributeMaxDynamicSharedMemorySize, SMEM_BYTES);
        cudaFuncSetAttribute(gemm_h<false, false>,
                             cudaFuncAttributeMaxDynamicSharedMemorySize, SMEM_BYTES);
        attr_done = true;
    }

    const float scale = 1.0f / sqrtf((float)D_Q);

    // 0) merged prep: conversions (scale folded into Q) + weight transposes.
    prep_convert<<<2048, 256>>>(keyh, key, valh, value, qh, query,
                                MKV * D_C / 8, BATCH * L_Q * D_Q / 8, scale);
    prep_transpose<<<1024, 256>>>(wkT, Wk, wvT, Wv, woT, Wo);

    // 1) K projection: kproj[16384,512] = keyh @ wkT^T + bk (col bias), half out.
    gemm_h<true, false><<<dim3(D_Q / HBN, MKV / HBM, 1), 256, SMEM_BYTES>>>(
        keyh, wkT, kproj, bk, MKV, D_Q, D_C, D_C, D_C, D_Q, 0, 0, 0);

    // 2) V projection TRANSPOSED: vprT[512,16384] = wvT @ valh^T + bv (ROW bias).
    gemm_h<true, true><<<dim3(MKV / HBN, D_Q / HBM, 1), 256, SMEM_BYTES>>>(
        wvT, valh, vprT, bv, D_Q, MKV, D_C, D_C, D_C, MKV, 0, 0, 0);

    // 3) Scores per batch: qh_b[2048,512] @ kproj_b^T -> fp16 (scale pre-folded).
    gemm_h<true, false><<<dim3(L_KV / HBN, L_Q / HBM, BATCH), 256, SMEM_BYTES>>>(
        qh, kproj, sc, nullptr, L_Q, L_KV, D_Q, D_Q, D_Q, L_KV,
        (long)L_Q * D_Q, (long)L_KV * D_Q, (long)L_Q * L_KV);

    // 4) Softmax in place (fp16).
    softmax_h2048<<<BATCH * L_Q, 256>>>(sc);

    // 5) Context per batch: probs_b[2048,2048] @ (vprT[:, b])^T -> ctxh, half out.
    gemm_h<true, false><<<dim3(D_Q / HBN, L_Q / HBM, BATCH), 256, SMEM_BYTES>>>(
        sc, vprT, ctxh, nullptr, L_Q, D_Q, L_KV, L_KV, MKV, D_Q,
        (long)L_Q * L_KV, (long)L_KV, (long)L_Q * D_Q);

    // 6) Output projection: ctxh[16384,512] @ woT^T + bo -> fp32 out.
    gemm_h<false, false><<<dim3(D_Q / HBN, MKV / HBM, 1), 256, SMEM_BYTES>>>(
        ctxh, woT, out, bo, MKV, D_Q, D_Q, D_Q, D_Q, D_Q, 0, 0, 0);
}